// round 15
// baseline (speedup 1.0000x reference)
#include <cuda_runtime.h>
#include <cuda_bf16.h>
#include <math.h>
#include <stdint.h>

// ---------------- problem constants ----------------
#define BATCH 16
#define SEQ   1000
#define EMB   512
#define NH    8
#define DH    64
#define FF    2048
#define CBN   4096
#define NL    4
#define E3    1536
#define MTOK  (BATCH*SEQ)
#define NCAND 64

// converted-weight buffer layout (bytes)
#define WC_QKV  0
#define WC_OUT  (WC_QKV + (size_t)NL*E3*EMB*4)
#define WC_FF1  (WC_OUT + (size_t)NL*EMB*EMB*4)
#define WC_FF2  (WC_FF1 + (size_t)NL*FF*EMB*4)
#define WC_PP1  (WC_FF2 + (size_t)NL*EMB*FF*4)
#define WC_PP2  (WC_PP1 + (size_t)EMB*EMB*4)
#define WC_FC1  (WC_PP2 + (size_t)EMB*EMB*4)
#define WC_FC2  (WC_FC1 + (size_t)EMB*EMB*4)
#define WC_CB   (WC_FC2 + (size_t)EMB*EMB*4)
#define WC_TOTAL (WC_CB + (size_t)CBN*EMB*4)

// ---------------- scratch ----------------
__device__ __align__(16) static float g_x   [MTOK*EMB];
__device__ __align__(16) static float g_y   [MTOK*EMB];
__device__ __align__(16) static float g_h   [MTOK*EMB];
__device__ __align__(16) static float g_qkv [MTOK*E3];   // hilo bytes
__device__ __align__(16) static float g_ctx [MTOK*EMB];
__device__ __align__(16) static float g_t   [MTOK*FF];
__device__ __align__(16) static float g_enh [MTOK*EMB];
__device__ __align__(16) static float g_cbn2[CBN];
__device__ __align__(16) static int   g_pidx[MTOK*NCAND];
__device__ __align__(16) static uint8_t g_wc[WC_TOTAL];

// ================= helpers =================
__device__ __forceinline__ uint32_t smem_u32(const void* p) {
    uint32_t a;
    asm("{ .reg .u64 t; cvta.to.shared.u64 t, %1; cvt.u32.u64 %0, t; }" : "=r"(a) : "l"(p));
    return a;
}
__device__ __forceinline__ void ldsm4(uint32_t* r, uint32_t addr) {
    asm volatile("ldmatrix.sync.aligned.m8n8.x4.shared.b16 {%0,%1,%2,%3}, [%4];"
                 : "=r"(r[0]), "=r"(r[1]), "=r"(r[2]), "=r"(r[3]) : "r"(addr));
}
__device__ __forceinline__ void ldsm4t(uint32_t* r, uint32_t addr) {
    asm volatile("ldmatrix.sync.aligned.m8n8.x4.trans.shared.b16 {%0,%1,%2,%3}, [%4];"
                 : "=r"(r[0]), "=r"(r[1]), "=r"(r[2]), "=r"(r[3]) : "r"(addr));
}
__device__ __forceinline__ void mma_bf16(float* c, const uint32_t* a, const uint32_t* b) {
    asm volatile("mma.sync.aligned.m16n8k16.row.col.f32.bf16.bf16.f32 "
                 "{%0,%1,%2,%3}, {%4,%5,%6,%7}, {%8,%9}, {%0,%1,%2,%3};"
                 : "+f"(c[0]), "+f"(c[1]), "+f"(c[2]), "+f"(c[3])
                 : "r"(a[0]), "r"(a[1]), "r"(a[2]), "r"(a[3]), "r"(b[0]), "r"(b[1]));
}
__device__ __forceinline__ uint32_t sw128(uint32_t off) {
    return off ^ ((off >> 3) & 0x70);
}
__device__ __forceinline__ void cvt_hilo(float4 v, uint2& hi, uint2& lo) {
    uint32_t h0, h1;
    asm("cvt.rn.bf16x2.f32 %0, %1, %2;" : "=r"(h0) : "f"(v.y), "f"(v.x));
    asm("cvt.rn.bf16x2.f32 %0, %1, %2;" : "=r"(h1) : "f"(v.w), "f"(v.z));
    float hx = __uint_as_float(h0 << 16);
    float hy = __uint_as_float(h0 & 0xffff0000u);
    float hz = __uint_as_float(h1 << 16);
    float hw = __uint_as_float(h1 & 0xffff0000u);
    uint32_t l0, l1;
    asm("cvt.rn.bf16x2.f32 %0, %1, %2;" : "=r"(l0) : "f"(v.y - hy), "f"(v.x - hx));
    asm("cvt.rn.bf16x2.f32 %0, %1, %2;" : "=r"(l1) : "f"(v.w - hw), "f"(v.z - hz));
    hi = make_uint2(h0, h1);
    lo = make_uint2(l0, l1);
}
// pack 2 floats into bf16x2 hi + residual lo
__device__ __forceinline__ void pack_hilo2(float p0, float p1, uint32_t& hi, uint32_t& lo) {
    asm("cvt.rn.bf16x2.f32 %0, %1, %2;" : "=r"(hi) : "f"(p1), "f"(p0));
    float h0 = __uint_as_float(hi << 16);
    float h1 = __uint_as_float(hi & 0xffff0000u);
    asm("cvt.rn.bf16x2.f32 %0, %1, %2;" : "=r"(lo) : "f"(p1 - h1), "f"(p0 - h0));
}
// global hilo-format store of 2 consecutive values (col even)
__device__ __forceinline__ void st_hilo2(uint8_t* dst, size_t row, int K, int col,
                                         float v0, float v1) {
    uint32_t hi, lo;
    pack_hilo2(v0, v1, hi, lo);
    uint8_t* r = dst + row * (size_t)K * 4 + (size_t)(col >> 5) * 128 + (col & 31) * 2;
    *(uint32_t*)r = hi;
    *(uint32_t*)(r + 64) = lo;
}

#define CP_ASYNC16(dst, src) \
    asm volatile("cp.async.cg.shared.global [%0], [%1], 16;" :: "r"(dst), "l"(src))
#define CP_COMMIT() asm volatile("cp.async.commit_group;" ::: "memory")
#define CP_WAIT0()  asm volatile("cp.async.wait_group 0;" ::: "memory")
#define CP_WAIT1()  asm volatile("cp.async.wait_group 1;" ::: "memory")

// ---------------- merged weight prep (one launch for all segments) ----------------
#define NSEG 9
struct PrepArgs {
    const float* src[NSEG];
    unsigned long long dstoff[NSEG];
    int K[NSEG];
    int base[NSEG];     // prefix sum of total4
    int grand;          // total float4 count
};

__global__ void prep_all(PrepArgs a, uint8_t* __restrict__ wc)
{
    int i = blockIdx.x * blockDim.x + threadIdx.x;
    if (i >= a.grand) return;
    int s = 0;
    #pragma unroll
    for (int j = 1; j < NSEG; j++)
        if (i >= a.base[j]) s = j;
    int li = i - a.base[s];
    int K  = a.K[s];
    int kq = K >> 2;
    int row = li / kq;
    int c4  = li - row * kq;
    float4 v = ((const float4*)a.src[s])[li];
    uint2 hi, lo;
    cvt_hilo(v, hi, lo);
    int k0 = c4 * 4;
    uint8_t* r = wc + a.dstoff[s] + (size_t)row * K * 4 + (k0 >> 5) * 128;
    *(uint2*)(r + (k0 & 31) * 2)      = hi;
    *(uint2*)(r + (k0 & 31) * 2 + 64) = lo;
}

// ---------------- embed (x only) ----------------
__global__ void embed_kernel(const int* __restrict__ tok, const float* __restrict__ cb,
                             const float* __restrict__ pe, float* __restrict__ x)
{
    int i = blockIdx.x * blockDim.x + threadIdx.x;
    if (i >= MTOK * (EMB/4)) return;
    int row = i >> 7;
    int c4  = i & 127;
    int s   = row % SEQ;
    int tk  = tok[row];
    float4 a = *(const float4*)(cb + (size_t)tk * EMB + c4*4);
    float4 p = *(const float4*)(pe + (size_t)s  * EMB + c4*4);
    ((float4*)x)[i] = make_float4(a.x+p.x, a.y+p.y, a.z+p.z, a.w+p.w);
}

// ---------------- layernorm: warp-per-row, hilo output ----------------
__global__ void __launch_bounds__(256) ln_kernel(const float* __restrict__ in,
                                                 const float* __restrict__ gam,
                                                 const float* __restrict__ bet,
                                                 uint8_t* __restrict__ out, int dogelu)
{
    const int w    = threadIdx.x >> 5;
    const int lane = threadIdx.x & 31;
    const int row  = blockIdx.x * 8 + w;
    const float* rp = in + (size_t)row * EMB;

    float4 v[4];
    float s = 0.f, ss = 0.f;
    #pragma unroll
    for (int it = 0; it < 4; it++) {
        v[it] = *(const float4*)(rp + it*128 + lane*4);
        s  += v[it].x + v[it].y + v[it].z + v[it].w;
        ss += v[it].x*v[it].x + v[it].y*v[it].y + v[it].z*v[it].z + v[it].w*v[it].w;
    }
    #pragma unroll
    for (int off = 16; off; off >>= 1) {
        s  += __shfl_xor_sync(0xffffffffu, s,  off);
        ss += __shfl_xor_sync(0xffffffffu, ss, off);
    }
    float mean = s * (1.f / EMB);
    float var  = ss * (1.f / EMB) - mean * mean;
    float rstd = rsqrtf(var + 1e-5f);

    #pragma unroll
    for (int it = 0; it < 4; it++) {
        int col = it*128 + lane*4;
        float4 gv = *(const float4*)(gam + col);
        float4 bv = *(const float4*)(bet + col);
        float4 ov;
        ov.x = (v[it].x - mean) * rstd * gv.x + bv.x;
        ov.y = (v[it].y - mean) * rstd * gv.y + bv.y;
        ov.z = (v[it].z - mean) * rstd * gv.z + bv.z;
        ov.w = (v[it].w - mean) * rstd * gv.w + bv.w;
        if (dogelu) {
            ov.x *= normcdff(ov.x);
            ov.y *= normcdff(ov.y);
            ov.z *= normcdff(ov.z);
            ov.w *= normcdff(ov.w);
        }
        uint2 hi, lo;
        cvt_hilo(ov, hi, lo);
        uint8_t* r = out + (size_t)row * EMB * 4 + (col >> 5) * 128 + (col & 31) * 2;
        *(uint2*)r        = hi;
        *(uint2*)(r + 64) = lo;
    }
}

// ================= mma.sync GEMM (3-stage cp.async pipeline, RAW-free mma order) =================
#define STAGE3 32768
#define GEMM_SMEM (3*STAGE3 + 1024)

__device__ __forceinline__ void cpasync_tile(uint32_t dstbase, const uint8_t* __restrict__ src0,
                                             size_t rowbytes, int t)
{
    #pragma unroll
    for (int i = 0; i < 4; i++) {
        int idx = i * 256 + t;
        int row = idx >> 3, u = idx & 7;
        uint32_t dst = dstbase + sw128((uint32_t)(row * 128 + u * 16));
        CP_ASYNC16(dst, src0 + (size_t)row * rowbytes + u * 16);
    }
}

// MODE: 0 bias, 1 bias+GELU, 2 bias+resid, 3 resid+scale*(.+bias), 4 candidates
// OUTF: 0 fp32, 1 hilo, 2 both
template<int MODE, int OUTF>
__global__ void __launch_bounds__(256, 2) gemm_mma(
    const uint8_t* __restrict__ Ac, const uint8_t* __restrict__ Wc,
    const float* __restrict__ bias, float* __restrict__ C, uint8_t* __restrict__ Ch,
    int M, int N, int K,
    const float* __restrict__ resid, const float* __restrict__ scp,
    const float* __restrict__ cbn2, int* __restrict__ pidx)
{
    extern __shared__ char smraw[];
    uint32_t raw = smem_u32(smraw);
    uint32_t base = (raw + 1023) & ~1023u;
    char* sm0 = smraw + (base - raw);

    const int t    = threadIdx.x;
    const int lane = t & 31;
    const int w    = t >> 5;
    const int wm   = w >> 2;
    const int wn   = w & 3;
    const int m0 = blockIdx.y * 128;
    const int n0 = blockIdx.x * 128;
    const int chunks = K / 32;
    const size_t rowbytes = (size_t)K * 4;
    const uint8_t* Ab = Ac + (size_t)m0 * rowbytes;
    const uint8_t* Wb = Wc + (size_t)n0 * rowbytes;

    float acc[4][4][4];
    #pragma unroll
    for (int i = 0; i < 4; i++)
        #pragma unroll
        for (int j = 0; j < 4; j++)
            #pragma unroll
            for (int k = 0; k < 4; k++) acc[i][j][k] = 0.f;

    // prologue: stage chunks 0 and 1
    cpasync_tile(base,         Ab, rowbytes, t);
    cpasync_tile(base + 16384, Wb, rowbytes, t);
    CP_COMMIT();
    cpasync_tile(base + STAGE3,         Ab + 128, rowbytes, t);
    cpasync_tile(base + STAGE3 + 16384, Wb + 128, rowbytes, t);
    CP_COMMIT();
    CP_WAIT1();
    __syncthreads();

    const uint32_t aoff0 = (uint32_t)((wm * 64 + (lane & 15)) * 128 + (lane >> 4) * 16);
    const uint32_t boff0 = (uint32_t)((wn * 32 + ((lane >> 4) << 3) + (lane & 7)) * 128
                                      + ((lane >> 3) & 1) * 16);

    int cur = 0;
    for (int c = 0; c < chunks; c++) {
        if (c + 2 < chunks) {
            int nxt = cur + 2; if (nxt >= 3) nxt -= 3;
            uint32_t nb = base + (uint32_t)nxt * STAGE3;
            cpasync_tile(nb,         Ab + (size_t)(c + 2) * 128, rowbytes, t);
            cpasync_tile(nb + 16384, Wb + (size_t)(c + 2) * 128, rowbytes, t);
            CP_COMMIT();
        }

        uint32_t tA = base + (uint32_t)cur * STAGE3;
        uint32_t tB = tA + 16384;
        #pragma unroll
        for (int ks = 0; ks < 2; ks++) {
            uint32_t ah[4][4], al[4][4], bh[4][2], bl[4][2];
            #pragma unroll
            for (int mt = 0; mt < 4; mt++) {
                uint32_t offh = aoff0 + mt * (16 * 128) + ks * 32;
                ldsm4(ah[mt], tA + sw128(offh));
                ldsm4(al[mt], tA + sw128(offh + 64));
            }
            #pragma unroll
            for (int np = 0; np < 2; np++) {
                uint32_t offh = boff0 + np * (16 * 128) + ks * 32;
                uint32_t r[4];
                ldsm4(r, tB + sw128(offh));
                bh[np*2][0] = r[0]; bh[np*2][1] = r[1];
                bh[np*2+1][0] = r[2]; bh[np*2+1][1] = r[3];
                ldsm4(r, tB + sw128(offh + 64));
                bl[np*2][0] = r[0]; bl[np*2][1] = r[1];
                bl[np*2+1][0] = r[2]; bl[np*2+1][1] = r[3];
            }
            // term-outer emission: 16 independent accumulators per pass,
            // per-accumulator FP order unchanged (hh, hl, lh)
            #pragma unroll
            for (int mt = 0; mt < 4; mt++)
                #pragma unroll
                for (int nt = 0; nt < 4; nt++)
                    mma_bf16(acc[mt][nt], ah[mt], bh[nt]);
            #pragma unroll
            for (int mt = 0; mt < 4; mt++)
                #pragma unroll
                for (int nt = 0; nt < 4; nt++)
                    mma_bf16(acc[mt][nt], ah[mt], bl[nt]);
            #pragma unroll
            for (int mt = 0; mt < 4; mt++)
                #pragma unroll
                for (int nt = 0; nt < 4; nt++)
                    mma_bf16(acc[mt][nt], al[mt], bh[nt]);
        }
        if (c + 2 < chunks)      CP_WAIT1();
        else if (c + 1 < chunks) CP_WAIT0();
        __syncthreads();
        cur++; if (cur == 3) cur = 0;
    }

    if (MODE == 4) {
        float* psm = (float*)sm0;
        int*   pim = (int*)(sm0 + 128*4*2*4);
        #pragma unroll
        for (int mt = 0; mt < 4; mt++) {
            float b0[2] = {3.4e38f, 3.4e38f}, b1[2] = {3.4e38f, 3.4e38f};
            int   i0v[2] = {0x7fffffff, 0x7fffffff}, i1v[2] = {0x7fffffff, 0x7fffffff};
            #pragma unroll
            for (int nt = 0; nt < 4; nt++) {
                int n = n0 + wn * 32 + nt * 8 + (lane & 3) * 2;
                float c0 = cbn2[n], c1 = cbn2[n + 1];
                float dv[2][2];
                dv[0][0] = fmaf(-2.f, acc[mt][nt][0], c0);
                dv[0][1] = fmaf(-2.f, acc[mt][nt][1], c1);
                dv[1][0] = fmaf(-2.f, acc[mt][nt][2], c0);
                dv[1][1] = fmaf(-2.f, acc[mt][nt][3], c1);
                #pragma unroll
                for (int rr = 0; rr < 2; rr++)
                    #pragma unroll
                    for (int jj = 0; jj < 2; jj++) {
                        float d = dv[rr][jj]; int nn = n + jj;
                        if (d < b0[rr] || (d == b0[rr] && nn < i0v[rr])) {
                            b1[rr] = b0[rr]; i1v[rr] = i0v[rr];
                            b0[rr] = d; i0v[rr] = nn;
                        } else if (d < b1[rr] || (d == b1[rr] && nn < i1v[rr])) {
                            b1[rr] = d; i1v[rr] = nn;
                        }
                    }
            }
            #pragma unroll
            for (int off = 1; off < 4; off <<= 1) {
                #pragma unroll
                for (int rr = 0; rr < 2; rr++) {
                    float o0 = __shfl_xor_sync(0xffffffffu, b0[rr], off);
                    int   q0 = __shfl_xor_sync(0xffffffffu, i0v[rr], off);
                    float o1 = __shfl_xor_sync(0xffffffffu, b1[rr], off);
                    int   q1 = __shfl_xor_sync(0xffffffffu, i1v[rr], off);
                    if (o0 < b0[rr] || (o0 == b0[rr] && q0 < i0v[rr])) {
                        b1[rr] = b0[rr]; i1v[rr] = i0v[rr];
                        b0[rr] = o0; i0v[rr] = q0;
                    } else if (o0 < b1[rr] || (o0 == b1[rr] && q0 < i1v[rr])) {
                        b1[rr] = o0; i1v[rr] = q0;
                    }
                    if (o1 < b1[rr] || (o1 == b1[rr] && q1 < i1v[rr])) {
                        b1[rr] = o1; i1v[rr] = q1;
                    }
                }
            }
            if ((lane & 3) == 0) {
                int rl = wm * 64 + mt * 16 + (lane >> 2);
                psm[(rl*4 + wn)*2 + 0]     = b0[0]; pim[(rl*4 + wn)*2 + 0]     = i0v[0];
                psm[(rl*4 + wn)*2 + 1]     = b1[0]; pim[(rl*4 + wn)*2 + 1]     = i1v[0];
                psm[((rl+8)*4 + wn)*2 + 0] = b0[1]; pim[((rl+8)*4 + wn)*2 + 0] = i0v[1];
                psm[((rl+8)*4 + wn)*2 + 1] = b1[1]; pim[((rl+8)*4 + wn)*2 + 1] = i1v[1];
            }
        }
        __syncthreads();
        if (t < 128) {
            float b0 = 3.4e38f, b1 = 3.4e38f;
            int i0 = 0x7fffffff, i1 = 0x7fffffff;
            #pragma unroll
            for (int j = 0; j < 8; j++) {
                float v = psm[t*8 + j]; int id = pim[t*8 + j];
                if (v < b0 || (v == b0 && id < i0)) {
                    b1 = b0; i1 = i0; b0 = v; i0 = id;
                } else if (v < b1 || (v == b1 && id < i1)) {
                    b1 = v; i1 = id;
                }
            }
            size_t o = (size_t)(m0 + t) * NCAND + blockIdx.x * 2;
            pidx[o]     = i0;
            pidx[o + 1] = i1;
        }
        return;
    }

    const float scv = (MODE == 3) ? *scp : 1.f;
    #pragma unroll
    for (int mt = 0; mt < 4; mt++) {
        int rb = m0 + wm * 64 + mt * 16 + (lane >> 2);
        #pragma unroll
        for (int nt = 0; nt < 4; nt++) {
            int col = n0 + wn * 32 + nt * 8 + (lane & 3) * 2;
            float b0 = bias[col], b1 = bias[col + 1];
            float v0 = acc[mt][nt][0] + b0;
            float v1 = acc[mt][nt][1] + b1;
            float v2 = acc[mt][nt][2] + b0;
            float v3 = acc[mt][nt][3] + b1;
            size_t o0 = (size_t)rb * N + col;
            size_t o1 = (size_t)(rb + 8) * N + col;
            if (MODE == 1) {
                v0 *= normcdff(v0); v1 *= normcdff(v1);
                v2 *= normcdff(v2); v3 *= normcdff(v3);
            }
            if (MODE == 2) {
                v0 += resid[o0]; v1 += resid[o0 + 1];
                v2 += resid[o1]; v3 += resid[o1 + 1];
            }
            if (MODE == 3) {
                v0 = resid[o0] + scv * v0; v1 = resid[o0 + 1] + scv * v1;
                v2 = resid[o1] + scv * v2; v3 = resid[o1 + 1] + scv * v3;
            }
            if (OUTF == 0 || OUTF == 2) {
                *(float2*)(C + o0) = make_float2(v0, v1);
                *(float2*)(C + o1) = make_float2(v2, v3);
            }
            if (OUTF == 1 || OUTF == 2) {
                st_hilo2(Ch, (size_t)rb,     N, col, v0, v1);
                st_hilo2(Ch, (size_t)rb + 8, N, col, v2, v3);
            }
        }
    }
}

// ================= warp-autonomous flash attention, k-tile 64, 2 CTAs/SM =================
#define NKT 16
#define AQ_OFF   0          // 32 KB
#define AK_OFF   32768      // 2 x 16 KB
#define AV_OFF   65536      // 2 x 16 KB
#define ATT_SMEM 98304

__device__ __forceinline__ void attn_cp_tile64(uint32_t dstbase, const uint8_t* __restrict__ gq,
                                               int row0, int chunk0, int t)
{
    #pragma unroll
    for (int ch = 0; ch < 2; ch++) {
        #pragma unroll
        for (int i = 0; i < 2; i++) {
            int idx = i * 256 + t;
            int row = idx >> 3, u = idx & 7;
            int gr = row0 + row;
            if (gr > SEQ - 1) gr = SEQ - 1;
            uint32_t dst = dstbase + ch * 8192 + sw128((uint32_t)(row * 128 + u * 16));
            CP_ASYNC16(dst, gq + (size_t)gr * (E3 * 4) + (chunk0 + ch) * 128 + u * 16);
        }
    }
}
__device__ __forceinline__ void attn_cp_q(uint32_t dstbase, const uint8_t* __restrict__ gq,
                                          int row0, int chunk0, int t)
{
    #pragma unroll
    for (int ch = 0; ch < 2; ch++) {
        #pragma unroll
        for (int i = 0; i < 4; i++) {
            int idx = i * 256 + t;
            int row = idx >> 3, u = idx & 7;
            int gr = row0 + row;
            if (gr > SEQ - 1) gr = SEQ - 1;
            uint32_t dst = dstbase + ch * 16384 + sw128((uint32_t)(row * 128 + u * 16));
            CP_ASYNC16(dst, gq + (size_t)gr * (E3 * 4) + (chunk0 + ch) * 128 + u * 16);
        }
    }
}

__global__ void __launch_bounds__(256, 2) attn_mma(const uint8_t* __restrict__ qkv_h,
                                                   uint8_t* __restrict__ ctx_h)
{
    extern __shared__ char smraw[];
    uint32_t raw = smem_u32(smraw);
    uint32_t base = (raw + 1023) & ~1023u;

    const int t    = threadIdx.x;
    const int lane = t & 31;
    const int w    = t >> 5;
    const int q0 = blockIdx.x * 128;
    const int h  = blockIdx.y, b = blockIdx.z;
    const uint8_t* gq = qkv_h + (size_t)(b * SEQ) * (E3 * 4);
    const int qc = 2 * h;
    const int kc = (EMB / 32) + 2 * h;
    const int vc = (2 * EMB / 32) + 2 * h;

    attn_cp_q(base + AQ_OFF, gq, q0, qc, t);
    attn_cp_tile64(base + AK_OFF, gq, 0, kc, t);
    attn_cp_tile64(base + AV_OFF, gq, 0, vc, t);
    CP_COMMIT();
    CP_WAIT0();
    __syncthreads();

    float m0 = -1e30f, m1 = -1e30f, l0 = 0.f, l1 = 0.f;
    float acc_o[8][4];
    #pragma unroll
    for (int i = 0; i < 8; i++)
        #pragma unroll
        for (int j = 0; j < 4; j++) acc_o[i][j] = 0.f;

    const uint32_t aoffQ = (uint32_t)((w*16 + (lane & 15)) * 128 + ((lane >> 4) << 4));
    const uint32_t boffK = (uint32_t)((((lane >> 4) << 3) + (lane & 7)) * 128
                                      + (((lane >> 3) & 1) << 4));
    const uint32_t voff0 = (uint32_t)((lane & 15) * 128 + ((lane >> 4) << 4));

    for (int kt = 0; kt < NKT; kt++) {
        const int kb = kt & 1;
        const bool pre = (kt + 1 < NKT);
        if (pre) {
            attn_cp_tile64(base + AK_OFF + (kb ^ 1) * 16384, gq, (kt + 1) * 64, kc, t);
            attn_cp_tile64(base + AV_OFF + (kb ^ 1) * 16384, gq, (kt + 1) * 64, vc, t);
            CP_COMMIT();
        }

        float sacc[8][4];
        #pragma unroll
        for (int i = 0; i < 8; i++)
            #pragma unroll
            for (int j = 0; j < 4; j++) sacc[i][j] = 0.f;

        uint32_t tQ = base + AQ_OFF;
        uint32_t tK = base + AK_OFF + kb * 16384;
        #pragma unroll
        for (int ch = 0; ch < 2; ch++) {
            #pragma unroll
            for (int ks = 0; ks < 2; ks++) {
                uint32_t ah[4], al[4];
                uint32_t offA = aoffQ + ks * 32;
                ldsm4(ah, tQ + ch*16384 + sw128(offA));
                ldsm4(al, tQ + ch*16384 + sw128(offA + 64));
                #pragma unroll
                for (int nf = 0; nf < 4; nf++) {
                    uint32_t offB = boffK + nf * 2048 + ks * 32;
                    uint32_t rh[4], rl[4];
                    ldsm4(rh, tK + ch*8192 + sw128(offB));
                    ldsm4(rl, tK + ch*8192 + sw128(offB + 64));
                    uint32_t bh0[2] = {rh[0], rh[1]}, bh1[2] = {rh[2], rh[3]};
                    uint32_t bl0[2] = {rl[0], rl[1]}, bl1[2] = {rl[2], rl[3]};
                    // interleave acc pair; per-acc order preserved (hh, lh, hl)
                    mma_bf16(sacc[nf*2],   ah, bh0);
                    mma_bf16(sacc[nf*2+1], ah, bh1);
                    mma_bf16(sacc[nf*2],   al, bh0);
                    mma_bf16(sacc[nf*2+1], al, bh1);
                    mma_bf16(sacc[nf*2],   ah, bl0);
                    mma_bf16(sacc[nf*2+1], ah, bl1);
                }
            }
        }

        #pragma unroll
        for (int nt = 0; nt < 8; nt++)
            #pragma unroll
            for (int j = 0; j < 4; j++) sacc[nt][j] *= 0.125f;
        if (kt == NKT - 1) {
            #pragma unroll
            for (int nt = 0; nt < 8; nt++)
                #pragma unroll
                for (int j = 0; j < 2; j++) {
                    int col = kt*64 + nt*8 + (lane & 3)*2 + j;
                    if (col >= SEQ) {
                        sacc[nt][j]     = -1e30f;
                        sacc[nt][2 + j] = -1e30f;
                    }
                }
        }

        float mx0 = -1e30f, mx1 = -1e30f;
        #pragma unroll
        for (int nt = 0; nt < 8; nt++) {
            mx0 = fmaxf(mx0, fmaxf(sacc[nt][0], sacc[nt][1]));
            mx1 = fmaxf(mx1, fmaxf(sacc[nt][2], sacc[nt][3]));
        }
        mx0 = fmaxf(mx0, __shfl_xor_sync(0xffffffffu, mx0, 1));
        mx0 = fmaxf(mx0, __shfl_xor_sync(0xffffffffu, mx0, 2));
        mx1 = fmaxf(mx1, __shfl_xor_sync(0xffffffffu, mx1, 1));
        mx1 = fmaxf(mx1, __shfl_xor_sync(0xffffffffu, mx1, 2));
        float mn0 = fmaxf(m0, mx0), mn1 = fmaxf(m1, mx1);
        float al0 = __expf(m0 - mn0), al1 = __expf(m1 - mn1);
        m0 = mn0; m1 = mn1;
        float rs0 = 0.f, rs1 = 0.f;
        #pragma unroll
        for (int nt = 0; nt < 8; nt++) {
            sacc[nt][0] = __expf(sacc[nt][0] - mn0);
            sacc[nt][1] = __expf(sacc[nt][1] - mn0);
            sacc[nt][2] = __expf(sacc[nt][2] - mn1);
            sacc[nt][3] = __expf(sacc[nt][3] - mn1);
            rs0 += sacc[nt][0] + sacc[nt][1];
            rs1 += sacc[nt][2] + sacc[nt][3];
        }
        rs0 += __shfl_xor_sync(0xffffffffu, rs0, 1);
        rs0 += __shfl_xor_sync(0xffffffffu, rs0, 2);
        rs1 += __shfl_xor_sync(0xffffffffu, rs1, 1);
        rs1 += __shfl_xor_sync(0xffffffffu, rs1, 2);
        l0 = l0 * al0 + rs0;
        l1 = l1 * al1 + rs1;
        #pragma unroll
        for (int nt = 0; nt < 8; nt++) {
            acc_o[nt][0] *= al0; acc_o[nt][1] *= al0;
            acc_o[nt][2] *= al1; acc_o[nt][3] *= al1;
        }

        uint32_t tV = base + AV_OFF + kb * 16384;
        #pragma unroll
        for (int kf = 0; kf < 4; kf++) {
            uint32_t aph[4], apl[4];
            pack_hilo2(sacc[kf*2][0],   sacc[kf*2][1],   aph[0], apl[0]);
            pack_hilo2(sacc[kf*2][2],   sacc[kf*2][3],   aph[1], apl[1]);
            pack_hilo2(sacc[kf*2+1][0], sacc[kf*2+1][1], aph[2], apl[2]);
            pack_hilo2(sacc[kf*2+1][2], sacc[kf*2+1][3], aph[3], apl[3]);
            #pragma unroll
            for (int np = 0; np < 4; np++) {
                uint32_t voff = voff0 + kf*2048 + (np & 1)*32;
                uint32_t vb2 = tV + (np >> 1)*8192;
                uint32_t rh[4], rl[4];
                ldsm4t(rh, vb2 + sw128(voff));
                ldsm4t(rl, vb2 + sw128(voff + 64));
                uint32_t bh0[2] = {rh[0], rh[1]}, bh1[2] = {rh[2], rh[3]};
                uint32_t bl0[2] = {rl[0], rl[1]}, bl1[2] = {rl[2], rl[3]};
                // interleave acc pair; per-acc order preserved (ph·vh, pl·vh, ph·vl)
                mma_bf16(acc_o[np*2],   aph, bh0);
                mma_bf16(acc_o[np*2+1], aph, bh1);
                mma_bf16(acc_o[np*2],   apl, bh0);
                mma_bf16(acc_o[np*2+1], apl, bh1);
                mma_bf16(acc_o[np*2],   aph, bl0);
                mma_bf16(acc_o[np*2+1], aph, bl1);
            }
        }

        if (pre) CP_WAIT0();
        __syncthreads();
    }

    {
        float linv0 = 1.f / l0;
        float linv1 = 1.f / l1;
        int q1 = q0 + w*16 + (lane >> 2), q2 = q1 + 8;
        #pragma unroll
        for (int nt = 0; nt < 8; nt++) {
            int col = h*DH + nt*8 + (lane & 3)*2;
            if (q1 < SEQ)
                st_hilo2(ctx_h, (size_t)(b * SEQ + q1), EMB, col,
                         acc_o[nt][0]*linv0, acc_o[nt][1]*linv0);
            if (q2 < SEQ)
                st_hilo2(ctx_h, (size_t)(b * SEQ + q2), EMB, col,
                         acc_o[nt][2]*linv1, acc_o[nt][3]*linv1);
        }
    }
}

// ---------------- codebook squared norms ----------------
__global__ void sqnorm_kernel(const float* __restrict__ cb, float* __restrict__ out)
{
    int gid  = blockIdx.x * blockDim.x + threadIdx.x;
    int row  = gid >> 5, lane = gid & 31;
    if (row >= CBN) return;
    const float* r = cb + (size_t)row * EMB;
    float s = 0.f;
    for (int c = lane; c < EMB; c += 32) { float v = r[c]; s = fmaf(v, v, s); }
    #pragma unroll
    for (int off = 16; off; off >>= 1) s += __shfl_xor_sync(0xffffffffu, s, off);
    if (lane == 0) out[row] = s;
}

// ---------------- exact fp32 rescore ----------------
__global__ void __launch_bounds__(256) rescore_kernel(
    const float* __restrict__ fc, const float* __restrict__ cb,
    const float* __restrict__ cbn2, const int* __restrict__ cand,
    float* __restrict__ outTok)
{
    __shared__ float xs[EMB];
    __shared__ float wb[8];
    __shared__ int   wi[8];
    const int row = blockIdx.x;
    const int t = threadIdx.x, lane = t & 31, w = t >> 5;
    ((float2*)xs)[t] = ((const float2*)(fc + (size_t)row * EMB))[t];
    __syncthreads();
    float best = 3.4e38f; int bi = 0x7fffffff;
    #pragma unroll
    for (int k = 0; k < 8; k++) {
        int ci = cand[(size_t)row * NCAND + w * 8 + k];
        const float* c = cb + (size_t)ci * EMB;
        float dot = 0.f;
        #pragma unroll
        for (int e = 0; e < 16; e++)
            dot = fmaf(xs[lane + e*32], __ldg(c + lane + e*32), dot);
        #pragma unroll
        for (int off = 16; off; off >>= 1)
            dot += __shfl_xor_sync(0xffffffffu, dot, off);
        float d = fmaf(-2.f, dot, cbn2[ci]);
        if (d < best || (d == best && ci < bi)) { best = d; bi = ci; }
    }
    if (lane == 0) { wb[w] = best; wi[w] = bi; }
    __syncthreads();
    if (t == 0) {
        float b = wb[0]; int i0 = wi[0];
        #pragma unroll
        for (int j = 1; j < 8; j++)
            if (wb[j] < b || (wb[j] == b && wi[j] < i0)) { b = wb[j]; i0 = wi[j]; }
        outTok[row] = (float)i0;
    }
}

// ---------------- host orchestration ----------------
template<int MODE, int OUTF>
static inline void launch_gemm(const uint8_t* Ac, const uint8_t* Wc, const float* bias,
                               float* C, uint8_t* Ch, int M, int N, int K,
                               const float* resid, const float* sc,
                               const float* cbn2, int* pidx)
{
    dim3 grid(N / 128, M / 128);
    gemm_mma<MODE, OUTF><<<grid, 256, GEMM_SMEM>>>(Ac, Wc, bias, C, Ch, M, N, K,
                                                   resid, sc, cbn2, pidx);
}

extern "C" void kernel_launch(void* const* d_in, const int* in_sizes, int n_in,
                              void* d_out, int out_size)
{
    const int*   tok    = (const int*)  d_in[0];
    const float* cb     = (const float*)d_in[1];
    const float* pe     = (const float*)d_in[2];
    const float* qkv_w  = (const float*)d_in[3];
    const float* qkv_b  = (const float*)d_in[4];
    const float* out_w  = (const float*)d_in[5];
    const float* out_b  = (const float*)d_in[6];
    const float* ln1_g  = (const float*)d_in[7];
    const float* ln1_b  = (const float*)d_in[8];
    const float* ln2_g  = (const float*)d_in[9];
    const float* ln2_b  = (const float*)d_in[10];
    const float* ff1_w  = (const float*)d_in[11];
    const float* ff1_b  = (const float*)d_in[12];
    const float* ff2_w  = (const float*)d_in[13];
    const float* ff2_b  = (const float*)d_in[14];
    const float* fin_g  = (const float*)d_in[15];
    const float* fin_b  = (const float*)d_in[16];
    const float* pp1_w  = (const float*)d_in[17];
    const float* pp1_b  = (const float*)d_in[18];
    const float* ppln_g = (const float*)d_in[19];
    const float* ppln_b = (const float*)d_in[20];
    const float* pp2_w  = (const float*)d_in[21];
    const float* pp2_b  = (const float*)d_in[22];
    const float* res_w  = (const float*)d_in[23];
    const float* fc1_w  = (const float*)d_in[24];
    const float* fc1_b  = (const float*)d_in[25];
    const float* fcln_g = (const float*)d_in[26];
    const float* fcln_b = (const float*)d_in[27];
    const float* fc2_w  = (const float*)d_in[28];
    const float* fc2_b  = (const float*)d_in[29];

    float *x, *y, *hF, *qkvF, *ctxF, *tF, *enhF, *cbn2; int* pidx; uint8_t* wc;
    cudaGetSymbolAddress((void**)&x,    g_x);
    cudaGetSymbolAddress((void**)&y,    g_y);
    cudaGetSymbolAddress((void**)&hF,   g_h);
    cudaGetSymbolAddress((void**)&qkvF, g_qkv);
    cudaGetSymbolAddress((void**)&ctxF, g_ctx);
    cudaGetSymbolAddress((void**)&tF,   g_t);
    cudaGetSymbolAddress((void**)&enhF, g_enh);
    cudaGetSymbolAddress((void**)&cbn2, g_cbn2);
    cudaGetSymbolAddress((void**)&pidx, g_pidx);
    cudaGetSymbolAddress((void**)&wc,   g_wc);
    uint8_t* hH   = (uint8_t*)hF;
    uint8_t* qkvH = (uint8_t*)qkvF;
    uint8_t* ctxH = (uint8_t*)ctxF;
    uint8_t* tH   = (uint8_t*)tF;
    uint8_t* enhH = (uint8_t*)enhF;

    cudaFuncSetAttribute(attn_mma, cudaFuncAttributeMaxDynamicSharedMemorySize, ATT_SMEM);
    cudaFuncSetAttribute(gemm_mma<0,0>, cudaFuncAttributeMaxDynamicSharedMemorySize, GEMM_SMEM);
    cudaFuncSetAttribute(gemm_mma<0,1>, cudaFuncAttributeMaxDynamicSharedMemorySize, GEMM_SMEM);
    cudaFuncSetAttribute(gemm_mma<0,2>, cudaFuncAttributeMaxDynamicSharedMemorySize, GEMM_SMEM);
    cudaFuncSetAttribute(gemm_mma<1,1>, cudaFuncAttributeMaxDynamicSharedMemorySize, GEMM_SMEM);
    cudaFuncSetAttribute(gemm_mma<2,0>, cudaFuncAttributeMaxDynamicSharedMemorySize, GEMM_SMEM);
    cudaFuncSetAttribute(gemm_mma<3,1>, cudaFuncAttributeMaxDynamicSharedMemorySize, GEMM_SMEM);
    cudaFuncSetAttribute(gemm_mma<4,0>, cudaFuncAttributeMaxDynamicSharedMemorySize, GEMM_SMEM);

    float* fc_out = (float*)d_out;
    const int M = MTOK;

    // merged weight prep (single launch)
    {
        PrepArgs pa;
        const float* srcs[NSEG] = {qkv_w, out_w, ff1_w, ff2_w, pp1_w, pp2_w, fc1_w, fc2_w, cb};
        unsigned long long offs[NSEG] = {WC_QKV, WC_OUT, WC_FF1, WC_FF2, WC_PP1, WC_PP2, WC_FC1, WC_FC2, WC_CB};
        int Ns[NSEG] = {NL*E3, NL*EMB, NL*FF, NL*EMB, EMB, EMB, EMB, EMB, CBN};
        int Ks[NSEG] = {EMB, EMB, EMB, FF, EMB, EMB, EMB, EMB, EMB};
        int acc = 0;
        for (int s = 0; s < NSEG; s++) {
            pa.src[s] = srcs[s];
            pa.dstoff[s] = offs[s];
            pa.K[s] = Ks[s];
            pa.base[s] = acc;
            acc += Ns[s] * (Ks[s] / 4);
        }
        pa.grand = acc;
        prep_all<<<(acc + 255) / 256, 256>>>(pa, wc);
    }

    embed_kernel<<<(M * (EMB/4) + 255) / 256, 256>>>(tok, cb, pe, x);

    for (int l = 0; l < NL; l++) {
        const float* yin = (l == 0) ? x : y;
        ln_kernel<<<M/8, 256>>>(yin, ln1_g + l*EMB, ln1_b + l*EMB, hH, 0);
        launch_gemm<0,1>(hH, wc + WC_QKV + (size_t)l*E3*EMB*4, qkv_b + (size_t)l*E3,
                         nullptr, qkvH, M, E3, EMB, nullptr, nullptr, nullptr, nullptr);
        attn_mma<<<dim3((SEQ+127)/128, NH, BATCH), 256, ATT_SMEM>>>(qkvH, ctxH);
        launch_gemm<2,0>(ctxH, wc + WC_OUT + (size_t)l*EMB*EMB*4, out_b + (size_t)l*EMB,
                         y, nullptr, M, EMB, EMB, yin, nullptr, nullptr, nullptr);
        ln_kernel<<<M/8, 256>>>(y, ln2_g + l*EMB, ln2_b + l*EMB, hH, 0);
        launch_gemm<1,1>(hH, wc + WC_FF1 + (size_t)l*FF*EMB*4, ff1_b + (size_t)l*FF,
                         nullptr, tH, M, FF, EMB, nullptr, nullptr, nullptr, nullptr);
        launch_gemm<2,0>(tH, wc + WC_FF2 + (size_t)l*EMB*FF*4, ff2_b + (size_t)l*EMB,
                         y, nullptr, M, EMB, FF, y, nullptr, nullptr, nullptr);
    }

    ln_kernel<<<M/8, 256>>>(y, fin_g, fin_b, hH, 0);
    launch_gemm<0,0>(hH, wc + WC_PP1, pp1_b, ctxF, nullptr, M, EMB, EMB,
                     nullptr, nullptr, nullptr, nullptr);
    ln_kernel<<<M/8, 256>>>(ctxF, ppln_g, ppln_b, tH, 1);
    launch_gemm<3,1>(tH, wc + WC_PP2, pp2_b, nullptr, enhH, M, EMB, EMB,
                     x, res_w, nullptr, nullptr);
    launch_gemm<0,0>(enhH, wc + WC_FC1, fc1_b, ctxF, nullptr, M, EMB, EMB,
                     nullptr, nullptr, nullptr, nullptr);
    ln_kernel<<<M/8, 256>>>(ctxF, fcln_g, fcln_b, tH, 1);
    launch_gemm<0,2>(tH, wc + WC_FC2, fc2_b, fc_out, hH, M, EMB, EMB,
                     nullptr, nullptr, nullptr, nullptr);

    if (out_size >= MTOK * EMB + MTOK) {
        sqnorm_kernel<<<(CBN * 32 + 255) / 256, 256>>>(cb, cbn2);
        launch_gemm<4,0>(hH, wc + WC_CB, nullptr, nullptr, nullptr, M, CBN, EMB,
                         nullptr, nullptr, cbn2, pidx);
        rescore_kernel<<<MTOK, 256>>>(fc_out, cb, cbn2, pidx, fc_out + (size_t)MTOK * EMB);
    }
}

// round 16
// speedup vs baseline: 1.5505x; 1.5505x over previous
#include <cuda_runtime.h>
#include <cuda_bf16.h>
#include <math.h>
#include <stdint.h>

// ---------------- problem constants ----------------
#define BATCH 16
#define SEQ   1000
#define EMB   512
#define NH    8
#define DH    64
#define FF    2048
#define CBN   4096
#define NL    4
#define E3    1536
#define MTOK  (BATCH*SEQ)
#define NCAND 64

// converted-weight buffer layout (bytes)
#define WC_QKV  0
#define WC_OUT  (WC_QKV + (size_t)NL*E3*EMB*4)
#define WC_FF1  (WC_OUT + (size_t)NL*EMB*EMB*4)
#define WC_FF2  (WC_FF1 + (size_t)NL*FF*EMB*4)
#define WC_PP1  (WC_FF2 + (size_t)NL*EMB*FF*4)
#define WC_PP2  (WC_PP1 + (size_t)EMB*EMB*4)
#define WC_FC1  (WC_PP2 + (size_t)EMB*EMB*4)
#define WC_FC2  (WC_FC1 + (size_t)EMB*EMB*4)
#define WC_CB   (WC_FC2 + (size_t)EMB*EMB*4)
#define WC_TOTAL (WC_CB + (size_t)CBN*EMB*4)

// ---------------- scratch ----------------
__device__ __align__(16) static float g_x   [MTOK*EMB];
__device__ __align__(16) static float g_y   [MTOK*EMB];
__device__ __align__(16) static float g_h   [MTOK*EMB];
__device__ __align__(16) static float g_qkv [MTOK*E3];   // hilo bytes
__device__ __align__(16) static float g_ctx [MTOK*EMB];
__device__ __align__(16) static float g_t   [MTOK*FF];
__device__ __align__(16) static float g_enh [MTOK*EMB];
__device__ __align__(16) static float g_cbn2[CBN];
__device__ __align__(16) static int   g_pidx[MTOK*NCAND];
__device__ __align__(16) static uint8_t g_wc[WC_TOTAL];

// ================= helpers =================
__device__ __forceinline__ uint32_t smem_u32(const void* p) {
    uint32_t a;
    asm("{ .reg .u64 t; cvta.to.shared.u64 t, %1; cvt.u32.u64 %0, t; }" : "=r"(a) : "l"(p));
    return a;
}
__device__ __forceinline__ void ldsm4(uint32_t* r, uint32_t addr) {
    asm volatile("ldmatrix.sync.aligned.m8n8.x4.shared.b16 {%0,%1,%2,%3}, [%4];"
                 : "=r"(r[0]), "=r"(r[1]), "=r"(r[2]), "=r"(r[3]) : "r"(addr));
}
__device__ __forceinline__ void ldsm4t(uint32_t* r, uint32_t addr) {
    asm volatile("ldmatrix.sync.aligned.m8n8.x4.trans.shared.b16 {%0,%1,%2,%3}, [%4];"
                 : "=r"(r[0]), "=r"(r[1]), "=r"(r[2]), "=r"(r[3]) : "r"(addr));
}
__device__ __forceinline__ void mma_bf16(float* c, const uint32_t* a, const uint32_t* b) {
    asm volatile("mma.sync.aligned.m16n8k16.row.col.f32.bf16.bf16.f32 "
                 "{%0,%1,%2,%3}, {%4,%5,%6,%7}, {%8,%9}, {%0,%1,%2,%3};"
                 : "+f"(c[0]), "+f"(c[1]), "+f"(c[2]), "+f"(c[3])
                 : "r"(a[0]), "r"(a[1]), "r"(a[2]), "r"(a[3]), "r"(b[0]), "r"(b[1]));
}
__device__ __forceinline__ uint32_t sw128(uint32_t off) {
    return off ^ ((off >> 3) & 0x70);
}
__device__ __forceinline__ void cvt_hilo(float4 v, uint2& hi, uint2& lo) {
    uint32_t h0, h1;
    asm("cvt.rn.bf16x2.f32 %0, %1, %2;" : "=r"(h0) : "f"(v.y), "f"(v.x));
    asm("cvt.rn.bf16x2.f32 %0, %1, %2;" : "=r"(h1) : "f"(v.w), "f"(v.z));
    float hx = __uint_as_float(h0 << 16);
    float hy = __uint_as_float(h0 & 0xffff0000u);
    float hz = __uint_as_float(h1 << 16);
    float hw = __uint_as_float(h1 & 0xffff0000u);
    uint32_t l0, l1;
    asm("cvt.rn.bf16x2.f32 %0, %1, %2;" : "=r"(l0) : "f"(v.y - hy), "f"(v.x - hx));
    asm("cvt.rn.bf16x2.f32 %0, %1, %2;" : "=r"(l1) : "f"(v.w - hw), "f"(v.z - hz));
    hi = make_uint2(h0, h1);
    lo = make_uint2(l0, l1);
}
// pack 2 floats into bf16x2 hi + residual lo
__device__ __forceinline__ void pack_hilo2(float p0, float p1, uint32_t& hi, uint32_t& lo) {
    asm("cvt.rn.bf16x2.f32 %0, %1, %2;" : "=r"(hi) : "f"(p1), "f"(p0));
    float h0 = __uint_as_float(hi << 16);
    float h1 = __uint_as_float(hi & 0xffff0000u);
    asm("cvt.rn.bf16x2.f32 %0, %1, %2;" : "=r"(lo) : "f"(p1 - h1), "f"(p0 - h0));
}
// global hilo-format store of 2 consecutive values (col even)
__device__ __forceinline__ void st_hilo2(uint8_t* dst, size_t row, int K, int col,
                                         float v0, float v1) {
    uint32_t hi, lo;
    pack_hilo2(v0, v1, hi, lo);
    uint8_t* r = dst + row * (size_t)K * 4 + (size_t)(col >> 5) * 128 + (col & 31) * 2;
    *(uint32_t*)r = hi;
    *(uint32_t*)(r + 64) = lo;
}

#define CP_ASYNC16(dst, src) \
    asm volatile("cp.async.cg.shared.global [%0], [%1], 16;" :: "r"(dst), "l"(src))
#define CP_COMMIT() asm volatile("cp.async.commit_group;" ::: "memory")
#define CP_WAIT0()  asm volatile("cp.async.wait_group 0;" ::: "memory")
#define CP_WAIT1()  asm volatile("cp.async.wait_group 1;" ::: "memory")

// ---------------- merged weight prep (one launch for all segments) ----------------
#define NSEG 9
struct PrepArgs {
    const float* src[NSEG];
    unsigned long long dstoff[NSEG];
    int K[NSEG];
    int base[NSEG];     // prefix sum of total4
    int grand;          // total float4 count
};

__global__ void prep_all(PrepArgs a, uint8_t* __restrict__ wc)
{
    int i = blockIdx.x * blockDim.x + threadIdx.x;
    if (i >= a.grand) return;
    int s = 0;
    #pragma unroll
    for (int j = 1; j < NSEG; j++)
        if (i >= a.base[j]) s = j;
    int li = i - a.base[s];
    int K  = a.K[s];
    int kq = K >> 2;
    int row = li / kq;
    int c4  = li - row * kq;
    float4 v = ((const float4*)a.src[s])[li];
    uint2 hi, lo;
    cvt_hilo(v, hi, lo);
    int k0 = c4 * 4;
    uint8_t* r = wc + a.dstoff[s] + (size_t)row * K * 4 + (k0 >> 5) * 128;
    *(uint2*)(r + (k0 & 31) * 2)      = hi;
    *(uint2*)(r + (k0 & 31) * 2 + 64) = lo;
}

// ---------------- embed (x only) ----------------
__global__ void embed_kernel(const int* __restrict__ tok, const float* __restrict__ cb,
                             const float* __restrict__ pe, float* __restrict__ x)
{
    int i = blockIdx.x * blockDim.x + threadIdx.x;
    if (i >= MTOK * (EMB/4)) return;
    int row = i >> 7;
    int c4  = i & 127;
    int s   = row % SEQ;
    int tk  = tok[row];
    float4 a = *(const float4*)(cb + (size_t)tk * EMB + c4*4);
    float4 p = *(const float4*)(pe + (size_t)s  * EMB + c4*4);
    ((float4*)x)[i] = make_float4(a.x+p.x, a.y+p.y, a.z+p.z, a.w+p.w);
}

// ---------------- layernorm: warp-per-row, hilo output ----------------
__global__ void __launch_bounds__(256) ln_kernel(const float* __restrict__ in,
                                                 const float* __restrict__ gam,
                                                 const float* __restrict__ bet,
                                                 uint8_t* __restrict__ out, int dogelu)
{
    const int w    = threadIdx.x >> 5;
    const int lane = threadIdx.x & 31;
    const int row  = blockIdx.x * 8 + w;
    const float* rp = in + (size_t)row * EMB;

    float4 v[4];
    float s = 0.f, ss = 0.f;
    #pragma unroll
    for (int it = 0; it < 4; it++) {
        v[it] = *(const float4*)(rp + it*128 + lane*4);
        s  += v[it].x + v[it].y + v[it].z + v[it].w;
        ss += v[it].x*v[it].x + v[it].y*v[it].y + v[it].z*v[it].z + v[it].w*v[it].w;
    }
    #pragma unroll
    for (int off = 16; off; off >>= 1) {
        s  += __shfl_xor_sync(0xffffffffu, s,  off);
        ss += __shfl_xor_sync(0xffffffffu, ss, off);
    }
    float mean = s * (1.f / EMB);
    float var  = ss * (1.f / EMB) - mean * mean;
    float rstd = rsqrtf(var + 1e-5f);

    #pragma unroll
    for (int it = 0; it < 4; it++) {
        int col = it*128 + lane*4;
        float4 gv = *(const float4*)(gam + col);
        float4 bv = *(const float4*)(bet + col);
        float4 ov;
        ov.x = (v[it].x - mean) * rstd * gv.x + bv.x;
        ov.y = (v[it].y - mean) * rstd * gv.y + bv.y;
        ov.z = (v[it].z - mean) * rstd * gv.z + bv.z;
        ov.w = (v[it].w - mean) * rstd * gv.w + bv.w;
        if (dogelu) {
            ov.x *= normcdff(ov.x);
            ov.y *= normcdff(ov.y);
            ov.z *= normcdff(ov.z);
            ov.w *= normcdff(ov.w);
        }
        uint2 hi, lo;
        cvt_hilo(ov, hi, lo);
        uint8_t* r = out + (size_t)row * EMB * 4 + (col >> 5) * 128 + (col & 31) * 2;
        *(uint2*)r        = hi;
        *(uint2*)(r + 64) = lo;
    }
}

// ================= mma.sync GEMM (3-stage cp.async pipeline) =================
#define STAGE3 32768
#define GEMM_SMEM (3*STAGE3 + 1024)

__device__ __forceinline__ void cpasync_tile(uint32_t dstbase, const uint8_t* __restrict__ src0,
                                             size_t rowbytes, int t)
{
    #pragma unroll
    for (int i = 0; i < 4; i++) {
        int idx = i * 256 + t;
        int row = idx >> 3, u = idx & 7;
        uint32_t dst = dstbase + sw128((uint32_t)(row * 128 + u * 16));
        CP_ASYNC16(dst, src0 + (size_t)row * rowbytes + u * 16);
    }
}

// MODE: 0 bias, 1 bias+GELU, 2 bias+resid, 3 resid+scale*(.+bias), 4 candidates
// OUTF: 0 fp32, 1 hilo, 2 both
template<int MODE, int OUTF>
__global__ void __launch_bounds__(256, 2) gemm_mma(
    const uint8_t* __restrict__ Ac, const uint8_t* __restrict__ Wc,
    const float* __restrict__ bias, float* __restrict__ C, uint8_t* __restrict__ Ch,
    int M, int N, int K,
    const float* __restrict__ resid, const float* __restrict__ scp,
    const float* __restrict__ cbn2, int* __restrict__ pidx)
{
    extern __shared__ char smraw[];
    uint32_t raw = smem_u32(smraw);
    uint32_t base = (raw + 1023) & ~1023u;
    char* sm0 = smraw + (base - raw);

    const int t    = threadIdx.x;
    const int lane = t & 31;
    const int w    = t >> 5;
    const int wm   = w >> 2;
    const int wn   = w & 3;
    const int m0 = blockIdx.y * 128;
    const int n0 = blockIdx.x * 128;
    const int chunks = K / 32;
    const size_t rowbytes = (size_t)K * 4;
    const uint8_t* Ab = Ac + (size_t)m0 * rowbytes;
    const uint8_t* Wb = Wc + (size_t)n0 * rowbytes;

    float acc[4][4][4];
    #pragma unroll
    for (int i = 0; i < 4; i++)
        #pragma unroll
        for (int j = 0; j < 4; j++)
            #pragma unroll
            for (int k = 0; k < 4; k++) acc[i][j][k] = 0.f;

    // prologue: stage chunks 0 and 1
    cpasync_tile(base,         Ab, rowbytes, t);
    cpasync_tile(base + 16384, Wb, rowbytes, t);
    CP_COMMIT();
    cpasync_tile(base + STAGE3,         Ab + 128, rowbytes, t);
    cpasync_tile(base + STAGE3 + 16384, Wb + 128, rowbytes, t);
    CP_COMMIT();
    CP_WAIT1();   // chunk 0 ready; chunk 1 may still be in flight
    __syncthreads();

    const uint32_t aoff0 = (uint32_t)((wm * 64 + (lane & 15)) * 128 + (lane >> 4) * 16);
    const uint32_t boff0 = (uint32_t)((wn * 32 + ((lane >> 4) << 3) + (lane & 7)) * 128
                                      + ((lane >> 3) & 1) * 16);

    int cur = 0;
    for (int c = 0; c < chunks; c++) {
        if (c + 2 < chunks) {
            int nxt = cur + 2; if (nxt >= 3) nxt -= 3;
            uint32_t nb = base + (uint32_t)nxt * STAGE3;
            cpasync_tile(nb,         Ab + (size_t)(c + 2) * 128, rowbytes, t);
            cpasync_tile(nb + 16384, Wb + (size_t)(c + 2) * 128, rowbytes, t);
            CP_COMMIT();
        }

        uint32_t tA = base + (uint32_t)cur * STAGE3;
        uint32_t tB = tA + 16384;
        #pragma unroll
        for (int ks = 0; ks < 2; ks++) {
            uint32_t ah[4][4], al[4][4], bh[4][2], bl[4][2];
            #pragma unroll
            for (int mt = 0; mt < 4; mt++) {
                uint32_t offh = aoff0 + mt * (16 * 128) + ks * 32;
                ldsm4(ah[mt], tA + sw128(offh));
                ldsm4(al[mt], tA + sw128(offh + 64));
            }
            #pragma unroll
            for (int np = 0; np < 2; np++) {
                uint32_t offh = boff0 + np * (16 * 128) + ks * 32;
                uint32_t r[4];
                ldsm4(r, tB + sw128(offh));
                bh[np*2][0] = r[0]; bh[np*2][1] = r[1];
                bh[np*2+1][0] = r[2]; bh[np*2+1][1] = r[3];
                ldsm4(r, tB + sw128(offh + 64));
                bl[np*2][0] = r[0]; bl[np*2][1] = r[1];
                bl[np*2+1][0] = r[2]; bl[np*2+1][1] = r[3];
            }
            #pragma unroll
            for (int mt = 0; mt < 4; mt++)
                #pragma unroll
                for (int nt = 0; nt < 4; nt++) {
                    mma_bf16(acc[mt][nt], ah[mt], bh[nt]);
                    mma_bf16(acc[mt][nt], ah[mt], bl[nt]);
                    mma_bf16(acc[mt][nt], al[mt], bh[nt]);
                }
        }
        if (c + 2 < chunks)      CP_WAIT1();   // next chunk ready; c+2 may fly
        else if (c + 1 < chunks) CP_WAIT0();   // last copy must land
        __syncthreads();
        cur++; if (cur == 3) cur = 0;
    }

    if (MODE == 4) {
        float* psm = (float*)sm0;
        int*   pim = (int*)(sm0 + 128*4*2*4);
        #pragma unroll
        for (int mt = 0; mt < 4; mt++) {
            float b0[2] = {3.4e38f, 3.4e38f}, b1[2] = {3.4e38f, 3.4e38f};
            int   i0v[2] = {0x7fffffff, 0x7fffffff}, i1v[2] = {0x7fffffff, 0x7fffffff};
            #pragma unroll
            for (int nt = 0; nt < 4; nt++) {
                int n = n0 + wn * 32 + nt * 8 + (lane & 3) * 2;
                float c0 = cbn2[n], c1 = cbn2[n + 1];
                float dv[2][2];
                dv[0][0] = fmaf(-2.f, acc[mt][nt][0], c0);
                dv[0][1] = fmaf(-2.f, acc[mt][nt][1], c1);
                dv[1][0] = fmaf(-2.f, acc[mt][nt][2], c0);
                dv[1][1] = fmaf(-2.f, acc[mt][nt][3], c1);
                #pragma unroll
                for (int rr = 0; rr < 2; rr++)
                    #pragma unroll
                    for (int jj = 0; jj < 2; jj++) {
                        float d = dv[rr][jj]; int nn = n + jj;
                        if (d < b0[rr] || (d == b0[rr] && nn < i0v[rr])) {
                            b1[rr] = b0[rr]; i1v[rr] = i0v[rr];
                            b0[rr] = d; i0v[rr] = nn;
                        } else if (d < b1[rr] || (d == b1[rr] && nn < i1v[rr])) {
                            b1[rr] = d; i1v[rr] = nn;
                        }
                    }
            }
            #pragma unroll
            for (int off = 1; off < 4; off <<= 1) {
                #pragma unroll
                for (int rr = 0; rr < 2; rr++) {
                    float o0 = __shfl_xor_sync(0xffffffffu, b0[rr], off);
                    int   q0 = __shfl_xor_sync(0xffffffffu, i0v[rr], off);
                    float o1 = __shfl_xor_sync(0xffffffffu, b1[rr], off);
                    int   q1 = __shfl_xor_sync(0xffffffffu, i1v[rr], off);
                    if (o0 < b0[rr] || (o0 == b0[rr] && q0 < i0v[rr])) {
                        b1[rr] = b0[rr]; i1v[rr] = i0v[rr];
                        b0[rr] = o0; i0v[rr] = q0;
                    } else if (o0 < b1[rr] || (o0 == b1[rr] && q0 < i1v[rr])) {
                        b1[rr] = o0; i1v[rr] = q0;
                    }
                    if (o1 < b1[rr] || (o1 == b1[rr] && q1 < i1v[rr])) {
                        b1[rr] = o1; i1v[rr] = q1;
                    }
                }
            }
            if ((lane & 3) == 0) {
                int rl = wm * 64 + mt * 16 + (lane >> 2);
                psm[(rl*4 + wn)*2 + 0]     = b0[0]; pim[(rl*4 + wn)*2 + 0]     = i0v[0];
                psm[(rl*4 + wn)*2 + 1]     = b1[0]; pim[(rl*4 + wn)*2 + 1]     = i1v[0];
                psm[((rl+8)*4 + wn)*2 + 0] = b0[1]; pim[((rl+8)*4 + wn)*2 + 0] = i0v[1];
                psm[((rl+8)*4 + wn)*2 + 1] = b1[1]; pim[((rl+8)*4 + wn)*2 + 1] = i1v[1];
            }
        }
        __syncthreads();
        if (t < 128) {
            float b0 = 3.4e38f, b1 = 3.4e38f;
            int i0 = 0x7fffffff, i1 = 0x7fffffff;
            #pragma unroll
            for (int j = 0; j < 8; j++) {
                float v = psm[t*8 + j]; int id = pim[t*8 + j];
                if (v < b0 || (v == b0 && id < i0)) {
                    b1 = b0; i1 = i0; b0 = v; i0 = id;
                } else if (v < b1 || (v == b1 && id < i1)) {
                    b1 = v; i1 = id;
                }
            }
            size_t o = (size_t)(m0 + t) * NCAND + blockIdx.x * 2;
            pidx[o]     = i0;
            pidx[o + 1] = i1;
        }
        return;
    }

    const float scv = (MODE == 3) ? *scp : 1.f;
    #pragma unroll
    for (int mt = 0; mt < 4; mt++) {
        int rb = m0 + wm * 64 + mt * 16 + (lane >> 2);
        #pragma unroll
        for (int nt = 0; nt < 4; nt++) {
            int col = n0 + wn * 32 + nt * 8 + (lane & 3) * 2;
            float b0 = bias[col], b1 = bias[col + 1];
            float v0 = acc[mt][nt][0] + b0;
            float v1 = acc[mt][nt][1] + b1;
            float v2 = acc[mt][nt][2] + b0;
            float v3 = acc[mt][nt][3] + b1;
            size_t o0 = (size_t)rb * N + col;
            size_t o1 = (size_t)(rb + 8) * N + col;
            if (MODE == 1) {
                v0 *= normcdff(v0); v1 *= normcdff(v1);
                v2 *= normcdff(v2); v3 *= normcdff(v3);
            }
            if (MODE == 2) {
                v0 += resid[o0]; v1 += resid[o0 + 1];
                v2 += resid[o1]; v3 += resid[o1 + 1];
            }
            if (MODE == 3) {
                v0 = resid[o0] + scv * v0; v1 = resid[o0 + 1] + scv * v1;
                v2 = resid[o1] + scv * v2; v3 = resid[o1 + 1] + scv * v3;
            }
            if (OUTF == 0 || OUTF == 2) {
                *(float2*)(C + o0) = make_float2(v0, v1);
                *(float2*)(C + o1) = make_float2(v2, v3);
            }
            if (OUTF == 1 || OUTF == 2) {
                st_hilo2(Ch, (size_t)rb,     N, col, v0, v1);
                st_hilo2(Ch, (size_t)rb + 8, N, col, v2, v3);
            }
        }
    }
}

// ================= warp-autonomous flash attention, k-tile 64, 2 CTAs/SM =================
#define NKT 16
#define AQ_OFF   0          // 32 KB
#define AK_OFF   32768      // 2 x 16 KB
#define AV_OFF   65536      // 2 x 16 KB
#define ATT_SMEM 98304

__device__ __forceinline__ void attn_cp_tile64(uint32_t dstbase, const uint8_t* __restrict__ gq,
                                               int row0, int chunk0, int t)
{
    #pragma unroll
    for (int ch = 0; ch < 2; ch++) {
        #pragma unroll
        for (int i = 0; i < 2; i++) {
            int idx = i * 256 + t;
            int row = idx >> 3, u = idx & 7;
            int gr = row0 + row;
            if (gr > SEQ - 1) gr = SEQ - 1;
            uint32_t dst = dstbase + ch * 8192 + sw128((uint32_t)(row * 128 + u * 16));
            CP_ASYNC16(dst, gq + (size_t)gr * (E3 * 4) + (chunk0 + ch) * 128 + u * 16);
        }
    }
}
__device__ __forceinline__ void attn_cp_q(uint32_t dstbase, const uint8_t* __restrict__ gq,
                                          int row0, int chunk0, int t)
{
    #pragma unroll
    for (int ch = 0; ch < 2; ch++) {
        #pragma unroll
        for (int i = 0; i < 4; i++) {
            int idx = i * 256 + t;
            int row = idx >> 3, u = idx & 7;
            int gr = row0 + row;
            if (gr > SEQ - 1) gr = SEQ - 1;
            uint32_t dst = dstbase + ch * 16384 + sw128((uint32_t)(row * 128 + u * 16));
            CP_ASYNC16(dst, gq + (size_t)gr * (E3 * 4) + (chunk0 + ch) * 128 + u * 16);
        }
    }
}

__global__ void __launch_bounds__(256, 2) attn_mma(const uint8_t* __restrict__ qkv_h,
                                                   uint8_t* __restrict__ ctx_h)
{
    extern __shared__ char smraw[];
    uint32_t raw = smem_u32(smraw);
    uint32_t base = (raw + 1023) & ~1023u;

    const int t    = threadIdx.x;
    const int lane = t & 31;
    const int w    = t >> 5;
    const int q0 = blockIdx.x * 128;
    const int h  = blockIdx.y, b = blockIdx.z;
    const uint8_t* gq = qkv_h + (size_t)(b * SEQ) * (E3 * 4);
    const int qc = 2 * h;
    const int kc = (EMB / 32) + 2 * h;
    const int vc = (2 * EMB / 32) + 2 * h;

    attn_cp_q(base + AQ_OFF, gq, q0, qc, t);
    attn_cp_tile64(base + AK_OFF, gq, 0, kc, t);
    attn_cp_tile64(base + AV_OFF, gq, 0, vc, t);
    CP_COMMIT();
    CP_WAIT0();
    __syncthreads();

    float m0 = -1e30f, m1 = -1e30f, l0 = 0.f, l1 = 0.f;
    float acc_o[8][4];
    #pragma unroll
    for (int i = 0; i < 8; i++)
        #pragma unroll
        for (int j = 0; j < 4; j++) acc_o[i][j] = 0.f;

    const uint32_t aoffQ = (uint32_t)((w*16 + (lane & 15)) * 128 + ((lane >> 4) << 4));
    const uint32_t boffK = (uint32_t)((((lane >> 4) << 3) + (lane & 7)) * 128
                                      + (((lane >> 3) & 1) << 4));
    const uint32_t voff0 = (uint32_t)((lane & 15) * 128 + ((lane >> 4) << 4));

    for (int kt = 0; kt < NKT; kt++) {
        const int kb = kt & 1;
        const bool pre = (kt + 1 < NKT);
        if (pre) {
            attn_cp_tile64(base + AK_OFF + (kb ^ 1) * 16384, gq, (kt + 1) * 64, kc, t);
            attn_cp_tile64(base + AV_OFF + (kb ^ 1) * 16384, gq, (kt + 1) * 64, vc, t);
            CP_COMMIT();
        }

        float sacc[8][4];
        #pragma unroll
        for (int i = 0; i < 8; i++)
            #pragma unroll
            for (int j = 0; j < 4; j++) sacc[i][j] = 0.f;

        uint32_t tQ = base + AQ_OFF;
        uint32_t tK = base + AK_OFF + kb * 16384;
        #pragma unroll
        for (int ch = 0; ch < 2; ch++) {
            #pragma unroll
            for (int ks = 0; ks < 2; ks++) {
                uint32_t ah[4], al[4];
                uint32_t offA = aoffQ + ks * 32;
                ldsm4(ah, tQ + ch*16384 + sw128(offA));
                ldsm4(al, tQ + ch*16384 + sw128(offA + 64));
                #pragma unroll
                for (int nf = 0; nf < 4; nf++) {
                    uint32_t offB = boffK + nf * 2048 + ks * 32;
                    uint32_t rh[4], rl[4];
                    ldsm4(rh, tK + ch*8192 + sw128(offB));
                    ldsm4(rl, tK + ch*8192 + sw128(offB + 64));
                    uint32_t bh0[2] = {rh[0], rh[1]}, bh1[2] = {rh[2], rh[3]};
                    uint32_t bl0[2] = {rl[0], rl[1]}, bl1[2] = {rl[2], rl[3]};
                    mma_bf16(sacc[nf*2],   ah, bh0);
                    mma_bf16(sacc[nf*2],   al, bh0);
                    mma_bf16(sacc[nf*2],   ah, bl0);
                    mma_bf16(sacc[nf*2+1], ah, bh1);
                    mma_bf16(sacc[nf*2+1], al, bh1);
                    mma_bf16(sacc[nf*2+1], ah, bl1);
                }
            }
        }

        #pragma unroll
        for (int nt = 0; nt < 8; nt++)
            #pragma unroll
            for (int j = 0; j < 4; j++) sacc[nt][j] *= 0.125f;
        if (kt == NKT - 1) {
            #pragma unroll
            for (int nt = 0; nt < 8; nt++)
                #pragma unroll
                for (int j = 0; j < 2; j++) {
                    int col = kt*64 + nt*8 + (lane & 3)*2 + j;
                    if (col >= SEQ) {
                        sacc[nt][j]     = -1e30f;
                        sacc[nt][2 + j] = -1e30f;
                    }
                }
        }

        float mx0 = -1e30f, mx1 = -1e30f;
        #pragma unroll
        for (int nt = 0; nt < 8; nt++) {
            mx0 = fmaxf(mx0, fmaxf(sacc[nt][0], sacc[nt][1]));
            mx1 = fmaxf(mx1, fmaxf(sacc[nt][2], sacc[nt][3]));
        }
        mx0 = fmaxf(mx0, __shfl_xor_sync(0xffffffffu, mx0, 1));
        mx0 = fmaxf(mx0, __shfl_xor_sync(0xffffffffu, mx0, 2));
        mx1 = fmaxf(mx1, __shfl_xor_sync(0xffffffffu, mx1, 1));
        mx1 = fmaxf(mx1, __shfl_xor_sync(0xffffffffu, mx1, 2));
        float mn0 = fmaxf(m0, mx0), mn1 = fmaxf(m1, mx1);
        float al0 = __expf(m0 - mn0), al1 = __expf(m1 - mn1);
        m0 = mn0; m1 = mn1;
        float rs0 = 0.f, rs1 = 0.f;
        #pragma unroll
        for (int nt = 0; nt < 8; nt++) {
            sacc[nt][0] = __expf(sacc[nt][0] - mn0);
            sacc[nt][1] = __expf(sacc[nt][1] - mn0);
            sacc[nt][2] = __expf(sacc[nt][2] - mn1);
            sacc[nt][3] = __expf(sacc[nt][3] - mn1);
            rs0 += sacc[nt][0] + sacc[nt][1];
            rs1 += sacc[nt][2] + sacc[nt][3];
        }
        rs0 += __shfl_xor_sync(0xffffffffu, rs0, 1);
        rs0 += __shfl_xor_sync(0xffffffffu, rs0, 2);
        rs1 += __shfl_xor_sync(0xffffffffu, rs1, 1);
        rs1 += __shfl_xor_sync(0xffffffffu, rs1, 2);
        l0 = l0 * al0 + rs0;
        l1 = l1 * al1 + rs1;
        #pragma unroll
        for (int nt = 0; nt < 8; nt++) {
            acc_o[nt][0] *= al0; acc_o[nt][1] *= al0;
            acc_o[nt][2] *= al1; acc_o[nt][3] *= al1;
        }

        uint32_t tV = base + AV_OFF + kb * 16384;
        #pragma unroll
        for (int kf = 0; kf < 4; kf++) {
            uint32_t aph[4], apl[4];
            pack_hilo2(sacc[kf*2][0],   sacc[kf*2][1],   aph[0], apl[0]);
            pack_hilo2(sacc[kf*2][2],   sacc[kf*2][3],   aph[1], apl[1]);
            pack_hilo2(sacc[kf*2+1][0], sacc[kf*2+1][1], aph[2], apl[2]);
            pack_hilo2(sacc[kf*2+1][2], sacc[kf*2+1][3], aph[3], apl[3]);
            #pragma unroll
            for (int np = 0; np < 4; np++) {
                uint32_t voff = voff0 + kf*2048 + (np & 1)*32;
                uint32_t vb2 = tV + (np >> 1)*8192;
                uint32_t rh[4], rl[4];
                ldsm4t(rh, vb2 + sw128(voff));
                ldsm4t(rl, vb2 + sw128(voff + 64));
                uint32_t bh0[2] = {rh[0], rh[1]}, bh1[2] = {rh[2], rh[3]};
                uint32_t bl0[2] = {rl[0], rl[1]}, bl1[2] = {rl[2], rl[3]};
                mma_bf16(acc_o[np*2],   aph, bh0);
                mma_bf16(acc_o[np*2],   apl, bh0);
                mma_bf16(acc_o[np*2],   aph, bl0);
                mma_bf16(acc_o[np*2+1], aph, bh1);
                mma_bf16(acc_o[np*2+1], apl, bh1);
                mma_bf16(acc_o[np*2+1], aph, bl1);
            }
        }

        if (pre) CP_WAIT0();
        __syncthreads();
    }

    {
        float linv0 = 1.f / l0;
        float linv1 = 1.f / l1;
        int q1 = q0 + w*16 + (lane >> 2), q2 = q1 + 8;
        #pragma unroll
        for (int nt = 0; nt < 8; nt++) {
            int col = h*DH + nt*8 + (lane & 3)*2;
            if (q1 < SEQ)
                st_hilo2(ctx_h, (size_t)(b * SEQ + q1), EMB, col,
                         acc_o[nt][0]*linv0, acc_o[nt][1]*linv0);
            if (q2 < SEQ)
                st_hilo2(ctx_h, (size_t)(b * SEQ + q2), EMB, col,
                         acc_o[nt][2]*linv1, acc_o[nt][3]*linv1);
        }
    }
}

// ---------------- codebook squared norms ----------------
__global__ void sqnorm_kernel(const float* __restrict__ cb, float* __restrict__ out)
{
    int gid  = blockIdx.x * blockDim.x + threadIdx.x;
    int row  = gid >> 5, lane = gid & 31;
    if (row >= CBN) return;
    const float* r = cb + (size_t)row * EMB;
    float s = 0.f;
    for (int c = lane; c < EMB; c += 32) { float v = r[c]; s = fmaf(v, v, s); }
    #pragma unroll
    for (int off = 16; off; off >>= 1) s += __shfl_xor_sync(0xffffffffu, s, off);
    if (lane == 0) out[row] = s;
}

// ---------------- exact fp32 rescore ----------------
__global__ void __launch_bounds__(256) rescore_kernel(
    const float* __restrict__ fc, const float* __restrict__ cb,
    const float* __restrict__ cbn2, const int* __restrict__ cand,
    float* __restrict__ outTok)
{
    __shared__ float xs[EMB];
    __shared__ float wb[8];
    __shared__ int   wi[8];
    const int row = blockIdx.x;
    const int t = threadIdx.x, lane = t & 31, w = t >> 5;
    ((float2*)xs)[t] = ((const float2*)(fc + (size_t)row * EMB))[t];
    __syncthreads();
    float best = 3.4e38f; int bi = 0x7fffffff;
    #pragma unroll
    for (int k = 0; k < 8; k++) {
        int ci = cand[(size_t)row * NCAND + w * 8 + k];
        const float* c = cb + (size_t)ci * EMB;
        float dot = 0.f;
        #pragma unroll
        for (int e = 0; e < 16; e++)
            dot = fmaf(xs[lane + e*32], __ldg(c + lane + e*32), dot);
        #pragma unroll
        for (int off = 16; off; off >>= 1)
            dot += __shfl_xor_sync(0xffffffffu, dot, off);
        float d = fmaf(-2.f, dot, cbn2[ci]);
        if (d < best || (d == best && ci < bi)) { best = d; bi = ci; }
    }
    if (lane == 0) { wb[w] = best; wi[w] = bi; }
    __syncthreads();
    if (t == 0) {
        float b = wb[0]; int i0 = wi[0];
        #pragma unroll
        for (int j = 1; j < 8; j++)
            if (wb[j] < b || (wb[j] == b && wi[j] < i0)) { b = wb[j]; i0 = wi[j]; }
        outTok[row] = (float)i0;
    }
}

// ---------------- host orchestration ----------------
template<int MODE, int OUTF>
static inline void launch_gemm(const uint8_t* Ac, const uint8_t* Wc, const float* bias,
                               float* C, uint8_t* Ch, int M, int N, int K,
                               const float* resid, const float* sc,
                               const float* cbn2, int* pidx)
{
    dim3 grid(N / 128, M / 128);
    gemm_mma<MODE, OUTF><<<grid, 256, GEMM_SMEM>>>(Ac, Wc, bias, C, Ch, M, N, K,
                                                   resid, sc, cbn2, pidx);
}

extern "C" void kernel_launch(void* const* d_in, const int* in_sizes, int n_in,
                              void* d_out, int out_size)
{
    const int*   tok    = (const int*)  d_in[0];
    const float* cb     = (const float*)d_in[1];
    const float* pe     = (const float*)d_in[2];
    const float* qkv_w  = (const float*)d_in[3];
    const float* qkv_b  = (const float*)d_in[4];
    const float* out_w  = (const float*)d_in[5];
    const float* out_b  = (const float*)d_in[6];
    const float* ln1_g  = (const float*)d_in[7];
    const float* ln1_b  = (const float*)d_in[8];
    const float* ln2_g  = (const float*)d_in[9];
    const float* ln2_b  = (const float*)d_in[10];
    const float* ff1_w  = (const float*)d_in[11];
    const float* ff1_b  = (const float*)d_in[12];
    const float* ff2_w  = (const float*)d_in[13];
    const float* ff2_b  = (const float*)d_in[14];
    const float* fin_g  = (const float*)d_in[15];
    const float* fin_b  = (const float*)d_in[16];
    const float* pp1_w  = (const float*)d_in[17];
    const float* pp1_b  = (const float*)d_in[18];
    const float* ppln_g = (const float*)d_in[19];
    const float* ppln_b = (const float*)d_in[20];
    const float* pp2_w  = (const float*)d_in[21];
    const float* pp2_b  = (const float*)d_in[22];
    const float* res_w  = (const float*)d_in[23];
    const float* fc1_w  = (const float*)d_in[24];
    const float* fc1_b  = (const float*)d_in[25];
    const float* fcln_g = (const float*)d_in[26];
    const float* fcln_b = (const float*)d_in[27];
    const float* fc2_w  = (const float*)d_in[28];
    const float* fc2_b  = (const float*)d_in[29];

    float *x, *y, *hF, *qkvF, *ctxF, *tF, *enhF, *cbn2; int* pidx; uint8_t* wc;
    cudaGetSymbolAddress((void**)&x,    g_x);
    cudaGetSymbolAddress((void**)&y,    g_y);
    cudaGetSymbolAddress((void**)&hF,   g_h);
    cudaGetSymbolAddress((void**)&qkvF, g_qkv);
    cudaGetSymbolAddress((void**)&ctxF, g_ctx);
    cudaGetSymbolAddress((void**)&tF,   g_t);
    cudaGetSymbolAddress((void**)&enhF, g_enh);
    cudaGetSymbolAddress((void**)&cbn2, g_cbn2);
    cudaGetSymbolAddress((void**)&pidx, g_pidx);
    cudaGetSymbolAddress((void**)&wc,   g_wc);
    uint8_t* hH   = (uint8_t*)hF;
    uint8_t* qkvH = (uint8_t*)qkvF;
    uint8_t* ctxH = (uint8_t*)ctxF;
    uint8_t* tH   = (uint8_t*)tF;
    uint8_t* enhH = (uint8_t*)enhF;

    cudaFuncSetAttribute(attn_mma, cudaFuncAttributeMaxDynamicSharedMemorySize, ATT_SMEM);
    cudaFuncSetAttribute(gemm_mma<0,0>, cudaFuncAttributeMaxDynamicSharedMemorySize, GEMM_SMEM);
    cudaFuncSetAttribute(gemm_mma<0,1>, cudaFuncAttributeMaxDynamicSharedMemorySize, GEMM_SMEM);
    cudaFuncSetAttribute(gemm_mma<0,2>, cudaFuncAttributeMaxDynamicSharedMemorySize, GEMM_SMEM);
    cudaFuncSetAttribute(gemm_mma<1,1>, cudaFuncAttributeMaxDynamicSharedMemorySize, GEMM_SMEM);
    cudaFuncSetAttribute(gemm_mma<2,0>, cudaFuncAttributeMaxDynamicSharedMemorySize, GEMM_SMEM);
    cudaFuncSetAttribute(gemm_mma<3,1>, cudaFuncAttributeMaxDynamicSharedMemorySize, GEMM_SMEM);
    cudaFuncSetAttribute(gemm_mma<4,0>, cudaFuncAttributeMaxDynamicSharedMemorySize, GEMM_SMEM);

    float* fc_out = (float*)d_out;
    const int M = MTOK;

    // merged weight prep (single launch)
    {
        PrepArgs pa;
        const float* srcs[NSEG] = {qkv_w, out_w, ff1_w, ff2_w, pp1_w, pp2_w, fc1_w, fc2_w, cb};
        unsigned long long offs[NSEG] = {WC_QKV, WC_OUT, WC_FF1, WC_FF2, WC_PP1, WC_PP2, WC_FC1, WC_FC2, WC_CB};
        int Ns[NSEG] = {NL*E3, NL*EMB, NL*FF, NL*EMB, EMB, EMB, EMB, EMB, CBN};
        int Ks[NSEG] = {EMB, EMB, EMB, FF, EMB, EMB, EMB, EMB, EMB};
        int acc = 0;
        for (int s = 0; s < NSEG; s++) {
            pa.src[s] = srcs[s];
            pa.dstoff[s] = offs[s];
            pa.K[s] = Ks[s];
            pa.base[s] = acc;
            acc += Ns[s] * (Ks[s] / 4);
        }
        pa.grand = acc;
        prep_all<<<(acc + 255) / 256, 256>>>(pa, wc);
    }

    embed_kernel<<<(M * (EMB/4) + 255) / 256, 256>>>(tok, cb, pe, x);

    for (int l = 0; l < NL; l++) {
        const float* yin = (l == 0) ? x : y;
        ln_kernel<<<M/8, 256>>>(yin, ln1_g + l*EMB, ln1_b + l*EMB, hH, 0);
        launch_gemm<0,1>(hH, wc + WC_QKV + (size_t)l*E3*EMB*4, qkv_b + (size_t)l*E3,
                         nullptr, qkvH, M, E3, EMB, nullptr, nullptr, nullptr, nullptr);
        attn_mma<<<dim3((SEQ+127)/128, NH, BATCH), 256, ATT_SMEM>>>(qkvH, ctxH);
        launch_gemm<2,0>(ctxH, wc + WC_OUT + (size_t)l*EMB*EMB*4, out_b + (size_t)l*EMB,
                         y, nullptr, M, EMB, EMB, yin, nullptr, nullptr, nullptr);
        ln_kernel<<<M/8, 256>>>(y, ln2_g + l*EMB, ln2_b + l*EMB, hH, 0);
        launch_gemm<1,1>(hH, wc + WC_FF1 + (size_t)l*FF*EMB*4, ff1_b + (size_t)l*FF,
                         nullptr, tH, M, FF, EMB, nullptr, nullptr, nullptr, nullptr);
        launch_gemm<2,0>(tH, wc + WC_FF2 + (size_t)l*EMB*FF*4, ff2_b + (size_t)l*EMB,
                         y, nullptr, M, EMB, FF, y, nullptr, nullptr, nullptr);
    }

    ln_kernel<<<M/8, 256>>>(y, fin_g, fin_b, hH, 0);
    launch_gemm<0,0>(hH, wc + WC_PP1, pp1_b, ctxF, nullptr, M, EMB, EMB,
                     nullptr, nullptr, nullptr, nullptr);
    ln_kernel<<<M/8, 256>>>(ctxF, ppln_g, ppln_b, tH, 1);
    launch_gemm<3,1>(tH, wc + WC_PP2, pp2_b, nullptr, enhH, M, EMB, EMB,
                     x, res_w, nullptr, nullptr);
    launch_gemm<0,0>(enhH, wc + WC_FC1, fc1_b, ctxF, nullptr, M, EMB, EMB,
                     nullptr, nullptr, nullptr, nullptr);
    ln_kernel<<<M/8, 256>>>(ctxF, fcln_g, fcln_b, tH, 1);
    launch_gemm<0,2>(tH, wc + WC_FC2, fc2_b, fc_out, hH, M, EMB, EMB,
                     nullptr, nullptr, nullptr, nullptr);

    if (out_size >= MTOK * EMB + MTOK) {
        sqnorm_kernel<<<(CBN * 32 + 255) / 256, 256>>>(cb, cbn2);
        launch_gemm<4,0>(hH, wc + WC_CB, nullptr, nullptr, nullptr, M, CBN, EMB,
                         nullptr, nullptr, cbn2, pidx);
        rescore_kernel<<<MTOK, 256>>>(fc_out, cb, cbn2, pidx, fc_out + (size_t)MTOK * EMB);
    }
}